// round 15
// baseline (speedup 1.0000x reference)
#include <cuda_runtime.h>
#include <cuda_fp16.h>
#include <cstdint>

// GraphNetBlock — mma.sync fp16 (m16n8k16, fp32 accum), v10 = v9 + gather prefetch:
//  * sender-proj gather issued in PROLOGUE directly into accumulators c
//    (addresses depend only on send[] -> no GEMM dependency). Latency hidden
//    under A-staging + other warps. Receiver gather stays in s0 epilogue.
//  * send/recv kept in 4 per-thread regs (same rows as final scatter) ->
//    sS/sR smem removed.
//  * otherwise v9: fp16 fragments, gmem-packed W via __ldg, 1 block barrier +
//    pair barriers, proj trick, TE=128, 2 CTAs/SM, red.v2, __stcs.

#define H 128
#define TE 128
#define THREADS 256

// smem: hA = 128 x 136 halves, then biases + LN stats
#define BIAS_F 8704              // 5 x 128 floats
#define STAT_F 9344              // sum[128], sq[128]
#define SMEM_FLOATS 9600
#define SMEM_BYTES (SMEM_FLOATS * 4)   // 38400 -> 2 CTAs/SM

__device__ float g_acc[50000 * H];
__device__ float g_proj[50000 * 384];
__device__ float4 g_wpk[9 * 2048];   // 9 packed 128x128 fp16 weight slices

__device__ __forceinline__ unsigned h2u(float lo, float hi) {
    __half2 h = __floats2half2_rn(lo, hi);
    return *(unsigned*)&h;
}
__device__ __forceinline__ void mma16(float c[4], const unsigned a[4], unsigned b0, unsigned b1) {
    asm volatile(
        "mma.sync.aligned.m16n8k16.row.col.f32.f16.f16.f32 "
        "{%0,%1,%2,%3}, {%4,%5,%6,%7}, {%8,%9}, {%0,%1,%2,%3};"
        : "+f"(c[0]), "+f"(c[1]), "+f"(c[2]), "+f"(c[3])
        : "r"(a[0]), "r"(a[1]), "r"(a[2]), "r"(a[3]), "r"(b0), "r"(b1));
}
__device__ __forceinline__ void red2(float* p, float a, float b) {
    asm volatile("red.global.add.v2.f32 [%0], {%1, %2};" :: "l"(p), "f"(a), "f"(b) : "memory");
}
__device__ __forceinline__ void pbar(int id) {
    asm volatile("bar.sync %0, 64;" :: "r"(id) : "memory");
}
__device__ __forceinline__ void zero_c(float c[16][4]) {
#pragma unroll
    for (int j = 0; j < 16; j++)
#pragma unroll
        for (int i = 0; i < 4; i++) c[j][i] = 0.f;
}

// ---- repack: W[k][n] (128x128 slices) -> fp16 fragment order ----
__global__ void repack_kernel(const float* __restrict__ eW0, const float* __restrict__ eW1,
                              const float* __restrict__ eW2, const float* __restrict__ nW0,
                              const float* __restrict__ nW1, const float* __restrict__ nW2) {
    int i = blockIdx.x * blockDim.x + threadIdx.x;
    if (i >= 9 * 2048) return;
    int m = i >> 11, r = i & 2047;
    int lane = r & 31, q = (r >> 5) & 3, wn = (r >> 7) & 1, kk = r >> 8;
    int g = lane >> 2, tig = lane & 3;
    const float* src;
    switch (m) {
        case 0: src = eW0; break;                // eW0_send
        case 1: src = eW0 + 128 * H; break;      // eW0_recv
        case 2: src = nW0; break;                // nW0_top
        case 3: src = eW0 + 256 * H; break;      // eW0_bot
        case 4: src = eW1; break;
        case 5: src = eW2; break;
        case 6: src = nW0 + 128 * H; break;      // nW0_bot
        case 7: src = nW1; break;
        default: src = nW2; break;
    }
    int kb = kk * 16 + 2 * tig;
    int n0 = wn * 64 + q * 16 + g;
    float4 o;
    *(unsigned*)&o.x = h2u(src[kb * H + n0],       src[(kb + 1) * H + n0]);
    *(unsigned*)&o.y = h2u(src[(kb + 8) * H + n0], src[(kb + 9) * H + n0]);
    *(unsigned*)&o.z = h2u(src[kb * H + n0 + 8],       src[(kb + 1) * H + n0 + 8]);
    *(unsigned*)&o.w = h2u(src[(kb + 8) * H + n0 + 8], src[(kb + 9) * H + n0 + 8]);
    g_wpk[i] = o;
}

// ---- full K=128 fp16 GEMM: A (half, stride 136) from smem, B via __ldg(L1) ----
__device__ __forceinline__ void mma_K128(float c[16][4], const __half* As,
                                         const float4* __restrict__ Wp,
                                         int wm, int wn, int g, int tig, int lane) {
#pragma unroll
    for (int kk = 0; kk < 8; kk++) {
        const float4* bp = Wp + ((kk * 2 + wn) * 4) * 32 + lane;
        float4 bq[4];
        bq[0] = __ldg(bp);
        bq[1] = __ldg(bp + 32);
        bq[2] = __ldg(bp + 64);
        bq[3] = __ldg(bp + 96);
        unsigned a0[4], a1[4];
        const __half* ap = As + (wm * 32 + g) * 136 + kk * 16 + 2 * tig;
        a0[0] = *(const unsigned*)(ap);
        a0[1] = *(const unsigned*)(ap + 8 * 136);
        a0[2] = *(const unsigned*)(ap + 8);
        a0[3] = *(const unsigned*)(ap + 8 * 136 + 8);
        a1[0] = *(const unsigned*)(ap + 16 * 136);
        a1[1] = *(const unsigned*)(ap + 24 * 136);
        a1[2] = *(const unsigned*)(ap + 16 * 136 + 8);
        a1[3] = *(const unsigned*)(ap + 24 * 136 + 8);
#pragma unroll
        for (int q = 0; q < 4; q++) {
            unsigned bx = *(const unsigned*)&bq[q].x, by = *(const unsigned*)&bq[q].y;
            unsigned bz = *(const unsigned*)&bq[q].z, bw = *(const unsigned*)&bq[q].w;
            mma16(c[2 * q],     a0, bx, by);
            mma16(c[2 * q + 1], a0, bz, bw);
            mma16(c[8 + 2 * q],     a1, bx, by);
            mma16(c[8 + 2 * q + 1], a1, bz, bw);
        }
    }
}

// ================= unified kernel: MODE 0=proj, 1=edge, 2=node =================
template <int MODE>
__global__ void __launch_bounds__(THREADS, 2)
gnb_kernel(const int* __restrict__ send, const int* __restrict__ recv,
           const float* __restrict__ nodef, const float* __restrict__ resid,
           float* __restrict__ acc, float* __restrict__ proj,
           const float4* __restrict__ Wa, const float4* __restrict__ Wb,
           const float4* __restrict__ Wc,
           const float* __restrict__ pb0, const float* __restrict__ pb1,
           const float* __restrict__ pb2,
           const float* __restrict__ gam, const float* __restrict__ bet,
           float* __restrict__ out, int rows) {
    extern __shared__ float sm[];
    __half* hA = (__half*)sm;                 // 128 x 136 halves
    float* sSum = sm + STAT_F;
    float* sSq  = sm + STAT_F + 128;

    const int tid = threadIdx.x, lane = tid & 31, warp = tid >> 5;
    const int g = lane >> 2, tig = lane & 3;
    const int wm = warp >> 1, wn = warp & 1;
    const int base = blockIdx.x * TE;
    const int nvalid = min(TE, rows - base);

    float c[16][4];
    int rv[4];   // receivers for this thread's 4 output rows (MODE 1)

    // ---- prologue: gather prefetch into c (MODE != 0) ----
    if (MODE != 0) {
#pragma unroll
        for (int mt = 0; mt < 2; mt++)
#pragma unroll
            for (int h = 0; h < 2; h++) {
                int r = wm * 32 + mt * 16 + g + 8 * h;
                int rg = min(base + r, rows - 1);
                const float* sp;
                if (MODE == 1) {
                    sp = proj + (size_t)__ldg(send + rg) * 384;
                    rv[mt * 2 + h] = __ldg(recv + rg);
                } else {
                    sp = proj + (size_t)rg * 384 + 256;
                }
#pragma unroll
                for (int jj = 0; jj < 8; jj++) {
                    int n0 = wn * 64 + jj * 8 + 2 * tig;
                    float2 av = *(const float2*)(sp + n0);
                    c[mt * 8 + jj][2 * h] = av.x;
                    c[mt * 8 + jj][2 * h + 1] = av.y;
                }
            }
    }

    // ---- biases + stats ----
    if (MODE != 0 && tid < H) {
        sm[BIAS_F + 0 * H + tid] = pb0[tid];
        sm[BIAS_F + 1 * H + tid] = pb1[tid];
        sm[BIAS_F + 2 * H + tid] = pb2[tid];
        sm[BIAS_F + 3 * H + tid] = gam[tid];
        sm[BIAS_F + 4 * H + tid] = bet[tid];
    }
    if (MODE != 0 && tid < 128) { sSum[tid] = 0.f; sSq[tid] = 0.f; }

    // ---- stage A tile (128 x 128 -> fp16, stride 136 halves) ----
#pragma unroll
    for (int i = 0; i < 16; i++) {
        int idx4 = tid + (i << 8);
        int r = idx4 >> 5;
        int c4 = (idx4 & 31) << 2;
        int rg = min(base + r, rows - 1);
        float4 v;
        if (MODE == 0) {
            v = *(const float4*)(nodef + (size_t)rg * H + c4);
        } else if (MODE == 1) {
            v = *(const float4*)(resid + (size_t)rg * H + c4);
        } else {
            float4* zp = (float4*)(acc + (size_t)rg * H + c4);
            v = *zp;
            if (base + r < rows) *zp = make_float4(0.f, 0.f, 0.f, 0.f);
        }
        uint2 pk;
        pk.x = h2u(v.x, v.y);
        pk.y = h2u(v.z, v.w);
        *(uint2*)(hA + r * 136 + c4) = pk;
    }
    __syncthreads();   // the ONLY block-wide barrier

#pragma unroll 1
    for (int s = 0; s < 3; s++) {
        const float4* Wp = (s == 0) ? Wa : (s == 1) ? Wb : Wc;
        if (s > 0 || MODE == 0) zero_c(c);
        mma_K128(c, hA, Wp, wm, wn, g, tig, lane);

        // ================= epilogues =================
        // c[mt*8 + jj], n0 = wn*64 + jj*8 + 2*tig, rows wm*32 + mt*16 + g + 8h
        if (MODE == 0) {
#pragma unroll
            for (int mt = 0; mt < 2; mt++)
#pragma unroll
                for (int h = 0; h < 2; h++) {
                    int r = wm * 32 + mt * 16 + g + 8 * h;
                    if (r < nvalid) {
                        float* p = proj + (size_t)(base + r) * 384 + s * 128;
#pragma unroll
                        for (int jj = 0; jj < 8; jj++) {
                            int n0 = wn * 64 + jj * 8 + 2 * tig;
                            *(float2*)(p + n0) =
                                make_float2(c[mt * 8 + jj][2 * h], c[mt * 8 + jj][2 * h + 1]);
                        }
                    }
                }
        } else if (s == 0) {
            pbar(1 + wm);   // pair partner done reading hA rows
            const float* bS = sm + BIAS_F;
#pragma unroll
            for (int mt = 0; mt < 2; mt++)
#pragma unroll
                for (int h = 0; h < 2; h++) {
                    int r = wm * 32 + mt * 16 + g + 8 * h;
                    const float* rp = nullptr;
                    if (MODE == 1)
                        rp = proj + (size_t)rv[mt * 2 + h] * 384 + 128;
#pragma unroll
                    for (int jj = 0; jj < 8; jj++) {
                        int n0 = wn * 64 + jj * 8 + 2 * tig;
                        float v0 = c[mt * 8 + jj][2 * h] + bS[n0];
                        float v1 = c[mt * 8 + jj][2 * h + 1] + bS[n0 + 1];
                        if (MODE == 1) {
                            float2 bv = *(const float2*)(rp + n0);
                            v0 += bv.x;
                            v1 += bv.y;
                        }
                        *(unsigned*)(hA + r * 136 + n0) =
                            h2u(fmaxf(v0, 0.f), fmaxf(v1, 0.f));
                    }
                }
            pbar(1 + wm);   // pair partner's hA writes visible
        } else if (s == 1) {
            pbar(1 + wm);
            const float* bS = sm + BIAS_F + H;
#pragma unroll
            for (int mt = 0; mt < 2; mt++)
#pragma unroll
                for (int h = 0; h < 2; h++) {
                    int r = wm * 32 + mt * 16 + g + 8 * h;
#pragma unroll
                    for (int jj = 0; jj < 8; jj++) {
                        int n0 = wn * 64 + jj * 8 + 2 * tig;
                        float v0 = c[mt * 8 + jj][2 * h] + bS[n0];
                        float v1 = c[mt * 8 + jj][2 * h + 1] + bS[n0 + 1];
                        *(unsigned*)(hA + r * 136 + n0) =
                            h2u(fmaxf(v0, 0.f), fmaxf(v1, 0.f));
                    }
                }
            pbar(1 + wm);
        } else {
            // ---- final: bias + LN (pair-combined) + residual + scatter ----
            const float* bS = sm + BIAS_F + 2 * H;
            float ps[2][2], pq[2][2];
#pragma unroll
            for (int mt = 0; mt < 2; mt++)
#pragma unroll
                for (int h = 0; h < 2; h++) {
                    float sacc = 0.f, qacc = 0.f;
#pragma unroll
                    for (int jj = 0; jj < 8; jj++) {
                        int n0 = wn * 64 + jj * 8 + 2 * tig;
                        float v0 = c[mt * 8 + jj][2 * h] + bS[n0];
                        float v1 = c[mt * 8 + jj][2 * h + 1] + bS[n0 + 1];
                        c[mt * 8 + jj][2 * h] = v0;
                        c[mt * 8 + jj][2 * h + 1] = v1;
                        sacc += v0 + v1;
                        qacc += v0 * v0 + v1 * v1;
                    }
                    ps[mt][h] = sacc;
                    pq[mt][h] = qacc;
                }
#pragma unroll
            for (int m = 1; m < 4; m <<= 1)
#pragma unroll
                for (int mt = 0; mt < 2; mt++)
#pragma unroll
                    for (int h = 0; h < 2; h++) {
                        ps[mt][h] += __shfl_xor_sync(0xffffffffu, ps[mt][h], m);
                        pq[mt][h] += __shfl_xor_sync(0xffffffffu, pq[mt][h], m);
                    }
            if (tig == 0) {
#pragma unroll
                for (int mt = 0; mt < 2; mt++)
#pragma unroll
                    for (int h = 0; h < 2; h++) {
                        int r = wm * 32 + mt * 16 + g + 8 * h;
                        atomicAdd(&sSum[r], ps[mt][h]);
                        atomicAdd(&sSq[r], pq[mt][h]);
                    }
            }
            pbar(1 + wm);   // pair stats complete
            const float* gS = sm + BIAS_F + 3 * H;
            const float* eS = sm + BIAS_F + 4 * H;
#pragma unroll
            for (int mt = 0; mt < 2; mt++)
#pragma unroll
                for (int h = 0; h < 2; h++) {
                    int r = wm * 32 + mt * 16 + g + 8 * h;
                    if (r >= nvalid) continue;
                    float mu = sSum[r] * (1.f / H);
                    float rs = rsqrtf(sSq[r] * (1.f / H) - mu * mu + 1e-5f);
                    size_t ro = (size_t)(base + r) * H;
                    int rc = (MODE == 1) ? rv[mt * 2 + h] : 0;
#pragma unroll
                    for (int jj = 0; jj < 8; jj++) {
                        int n0 = wn * 64 + jj * 8 + 2 * tig;
                        float y0 = (c[mt * 8 + jj][2 * h] - mu) * rs * gS[n0] + eS[n0];
                        float y1 = (c[mt * 8 + jj][2 * h + 1] - mu) * rs * gS[n0 + 1] + eS[n0 + 1];
                        float2 rf = *(const float2*)(resid + ro + n0);
                        __stcs((float2*)(out + ro + n0), make_float2(y0 + rf.x, y1 + rf.y));
                        if (MODE == 1) red2(&acc[(size_t)rc * H + n0], y0, y1);
                    }
                }
        }
    }
}

// ============================ LAUNCH ============================
extern "C" void kernel_launch(void* const* d_in, const int* in_sizes, int n_in,
                              void* d_out, int out_size) {
    const int*   senders   = (const int*)d_in[0];
    const int*   receivers = (const int*)d_in[1];
    const float* nodef     = (const float*)d_in[2];
    const float* edgef     = (const float*)d_in[3];
    const float* eW0 = (const float*)d_in[4];
    const float* eb0 = (const float*)d_in[5];
    const float* eW1 = (const float*)d_in[6];
    const float* eb1 = (const float*)d_in[7];
    const float* eW2 = (const float*)d_in[8];
    const float* eb2 = (const float*)d_in[9];
    const float* eg  = (const float*)d_in[10];
    const float* ebeta = (const float*)d_in[11];
    const float* nW0 = (const float*)d_in[12];
    const float* nb0 = (const float*)d_in[13];
    const float* nW1 = (const float*)d_in[14];
    const float* nb1 = (const float*)d_in[15];
    const float* nW2 = (const float*)d_in[16];
    const float* nb2 = (const float*)d_in[17];
    const float* ng  = (const float*)d_in[18];
    const float* nbeta = (const float*)d_in[19];

    int E = in_sizes[1];
    int N = in_sizes[2] / H;

    float* out_node = (float*)d_out;
    float* out_edge = out_node + (size_t)N * H;

    float *acc = nullptr, *proj = nullptr;
    float4* wpk = nullptr;
    cudaGetSymbolAddress((void**)&acc, g_acc);
    cudaGetSymbolAddress((void**)&proj, g_proj);
    cudaGetSymbolAddress((void**)&wpk, g_wpk);

    cudaFuncSetAttribute(gnb_kernel<0>, cudaFuncAttributeMaxDynamicSharedMemorySize, SMEM_BYTES);
    cudaFuncSetAttribute(gnb_kernel<1>, cudaFuncAttributeMaxDynamicSharedMemorySize, SMEM_BYTES);
    cudaFuncSetAttribute(gnb_kernel<2>, cudaFuncAttributeMaxDynamicSharedMemorySize, SMEM_BYTES);

    int ngrid = (N + TE - 1) / TE;
    int egrid = (E + TE - 1) / TE;

    repack_kernel<<<(9 * 2048 + 255) / 256, 256>>>(eW0, eW1, eW2, nW0, nW1, nW2);

    // proj: P = nodef @ [eW0_send | eW0_recv | nW0_top]
    gnb_kernel<0><<<ngrid, THREADS, SMEM_BYTES>>>(
        nullptr, nullptr, nodef, nullptr, acc, proj,
        wpk + 0 * 2048, wpk + 1 * 2048, wpk + 2 * 2048,
        eb0, eb0, eb0, eg, ebeta, nullptr, N);

    // edge MLP: ef @ eW0_bot (+gathered P) -> eW1 -> eW2 -> LN -> scatter
    gnb_kernel<1><<<egrid, THREADS, SMEM_BYTES>>>(
        senders, receivers, nodef, edgef, acc, proj,
        wpk + 3 * 2048, wpk + 4 * 2048, wpk + 5 * 2048,
        eb0, eb1, eb2, eg, ebeta, out_edge, E);

    // node MLP: acc @ nW0_bot (+P nf-block) -> nW1 -> nW2 -> LN
    gnb_kernel<2><<<ngrid, THREADS, SMEM_BYTES>>>(
        nullptr, nullptr, nodef, nodef, acc, proj,
        wpk + 6 * 2048, wpk + 7 * 2048, wpk + 8 * 2048,
        nb0, nb1, nb2, ng, nbeta, out_node, N);
}